// round 9
// baseline (speedup 1.0000x reference)
#include <cuda_runtime.h>
#include <cuda_fp16.h>
#include <cstdint>

#define B_ROWS   16384
#define D_DIM    256
#define T_TRIP   262144
#define MARGIN   0.1f
#define EPS_F    1e-6f
#define ROW_MASK (B_ROWS - 1)

#define WARPS_PER_BLOCK 8
#define ITERS 4
#define TRIPS_PER_ITER 2   // 16 lanes per triplet
// 4096 blocks * 8 warps * 4 iters * 2 triplets = 262144 == T_TRIP
#define TRIP_BLOCKS (T_TRIP / (WARPS_PER_BLOCK * ITERS * TRIPS_PER_ITER))

// Normalized fp16 copy of pred as uint4 (16B-aligned by type).
// Row = 256 halves = 32 uint4. 8 MB device-global scratch.
#define ROW_U4 (D_DIM / 8)
__device__ uint4 g_pred_q[B_ROWS * ROW_U4];

// Kernel 1: one warp per row -> normalized fp16 row. Zeroes d_out.
__global__ void __launch_bounds__(256)
tl_normalize_kernel(const float* __restrict__ pred, float* __restrict__ out)
{
    if (blockIdx.x == 0 && threadIdx.x == 0) out[0] = 0.0f;

    const int row  = (blockIdx.x * blockDim.x + threadIdx.x) >> 5;
    const int lane = threadIdx.x & 31;
    if (row >= B_ROWS) return;

    const float4* src = reinterpret_cast<const float4*>(pred + (size_t)row * D_DIM);
    float4 v0 = src[2 * lane];
    float4 v1 = src[2 * lane + 1];

    float s = v0.x*v0.x + v0.y*v0.y + v0.z*v0.z + v0.w*v0.w
            + v1.x*v1.x + v1.y*v1.y + v1.z*v1.z + v1.w*v1.w;
    #pragma unroll
    for (int o = 16; o > 0; o >>= 1)
        s += __shfl_xor_sync(0xFFFFFFFFu, s, o);

    const float inv = 1.0f / fmaxf(sqrtf(s), EPS_F);

    __half2 h0 = __floats2half2_rn(v0.x * inv, v0.y * inv);
    __half2 h1 = __floats2half2_rn(v0.z * inv, v0.w * inv);
    __half2 h2 = __floats2half2_rn(v1.x * inv, v1.y * inv);
    __half2 h3 = __floats2half2_rn(v1.z * inv, v1.w * inv);

    uint4 u;
    u.x = *reinterpret_cast<unsigned*>(&h0);
    u.y = *reinterpret_cast<unsigned*>(&h1);
    u.z = *reinterpret_cast<unsigned*>(&h2);
    u.w = *reinterpret_cast<unsigned*>(&h3);
    g_pred_q[row * ROW_U4 + lane] = u;
}

__device__ __forceinline__ __half2 u2h(unsigned u)
{
    __half2 h;
    *reinterpret_cast<unsigned*>(&h) = u;
    return h;
}

// dot(a, p - n) for 8 fp16 elems: fp16 products (one pairwise HADD2 level),
// fp32 final sums.
__device__ __forceinline__ float dot_diff8(uint4 a, uint4 p, uint4 n)
{
    __half2 m0 = __hmul2(u2h(a.x), __hsub2(u2h(p.x), u2h(n.x)));
    __half2 m1 = __hmul2(u2h(a.y), __hsub2(u2h(p.y), u2h(n.y)));
    __half2 m2 = __hmul2(u2h(a.z), __hsub2(u2h(p.z), u2h(n.z)));
    __half2 m3 = __hmul2(u2h(a.w), __hsub2(u2h(p.w), u2h(n.w)));
    float2 f01 = __half22float2(__hadd2(m0, m1));
    float2 f23 = __half22float2(__hadd2(m2, m3));
    return (f01.x + f01.y) + (f23.x + f23.y);
}

// Kernel 2: 16 lanes per triplet, 2 triplets per warp per iteration.
// Only 6 uint4 (24 regs) in flight -> fits 6 CTAs/SM (75% occupancy) to hide
// L2 gather latency. Row indices masked to [0, B_ROWS): OOB impossible.
__global__ void __launch_bounds__(WARPS_PER_BLOCK * 32, 6)
tl_triplet_kernel(const long long* __restrict__ anchor_idx,
                  const long long* __restrict__ pos_idx,
                  const long long* __restrict__ neg_idx,
                  float* __restrict__ out)
{
    const int lane = threadIdx.x & 31;
    const int wid  = threadIdx.x >> 5;
    const int seg  = lane >> 4;    // 0..1 : which triplet in this warp
    const int sub  = lane & 15;    // 0..15: position within triplet
    const int gwarp = blockIdx.x * WARPS_PER_BLOCK + wid;

    float acc = 0.0f;

    #pragma unroll
    for (int it = 0; it < ITERS; it++) {
        const int t = (gwarp * ITERS + it) * TRIPS_PER_ITER + seg;  // < T_TRIP

        const int a = ((int)anchor_idx[t]) & ROW_MASK;
        const int p = ((int)pos_idx[t])    & ROW_MASK;
        const int n = ((int)neg_idx[t])    & ROW_MASK;

        // Row = 32 uint4. Lane covers uint4 indices {sub, sub+16}.
        const uint4* ra = g_pred_q + a * ROW_U4 + sub;
        const uint4* rp = g_pred_q + p * ROW_U4 + sub;
        const uint4* rn = g_pred_q + n * ROW_U4 + sub;

        uint4 a0 = ra[0], a1 = ra[16];
        uint4 p0 = rp[0], p1 = rp[16];
        uint4 n0 = rn[0], n1 = rn[16];

        float s = dot_diff8(a0, p0, n0) + dot_diff8(a1, p1, n1);

        // Segmented butterfly within each 16-lane group.
        #pragma unroll
        for (int o = 1; o < 16; o <<= 1)
            s += __shfl_xor_sync(0xFFFFFFFFu, s, o);

        // Every lane of the segment holds the segment sum.
        acc += fmaxf(s + MARGIN, 0.0f);
    }

    // Combine the 2 segments (each counted once).
    acc += __shfl_xor_sync(0xFFFFFFFFu, acc, 16);

    __shared__ float sacc[WARPS_PER_BLOCK];
    if (lane == 0) sacc[wid] = acc;
    __syncthreads();

    if (threadIdx.x == 0) {
        float sum = 0.0f;
        #pragma unroll
        for (int i = 0; i < WARPS_PER_BLOCK; i++) sum += sacc[i];
        atomicAdd(out, sum * (1.0f / (float)T_TRIP));
    }
}

extern "C" void kernel_launch(void* const* d_in, const int* in_sizes, int n_in,
                              void* d_out, int out_size)
{
    const float*     pred = (const float*)d_in[0];
    const long long* ai   = (const long long*)d_in[1];
    const long long* pi   = (const long long*)d_in[2];
    const long long* ni   = (const long long*)d_in[3];
    float* out = (float*)d_out;

    tl_normalize_kernel<<<B_ROWS / 8, 256>>>(pred, out);
    tl_triplet_kernel<<<TRIP_BLOCKS, WARPS_PER_BLOCK * 32>>>(ai, pi, ni, out);
}

// round 11
// speedup vs baseline: 1.0760x; 1.0760x over previous
#include <cuda_runtime.h>
#include <cstdint>

#define B_ROWS   16384
#define D_DIM    256
#define T_TRIP   262144
#define MARGIN   0.1f
#define EPS_F    1e-6f
#define ROW_MASK (B_ROWS - 1)

#define WARPS_PER_BLOCK 8
#define ITERS 4
// each warp-iteration handles 4 triplets (8 lanes per triplet)
// 2048 blocks * 8 warps * 4 iters * 4 triplets = 262144 == T_TRIP
#define TRIP_BLOCKS (T_TRIP / (WARPS_PER_BLOCK * ITERS * 4))

// Normalized int8 copy of pred: row r = round(127 * pred[r]/max(||pred[r]||,eps)).
// Row = 256 int8 = 256 B = 16 uint4. 4 MB device-global scratch, 16B-aligned.
#define ROW_U4 (D_DIM / 16)
__device__ uint4 g_pred_b[B_ROWS * ROW_U4];

// Kernel 1: one warp per row -> normalized int8 row. Zeroes d_out.
__global__ void __launch_bounds__(256)
tl_normalize_kernel(const float* __restrict__ pred, float* __restrict__ out)
{
    if (blockIdx.x == 0 && threadIdx.x == 0) out[0] = 0.0f;

    const int row  = (blockIdx.x * blockDim.x + threadIdx.x) >> 5;
    const int lane = threadIdx.x & 31;
    if (row >= B_ROWS) return;

    // Lane handles 8 contiguous floats: [lane*8, lane*8+8).
    const float4* src = reinterpret_cast<const float4*>(pred + (size_t)row * D_DIM);
    float4 v0 = src[2 * lane];
    float4 v1 = src[2 * lane + 1];

    float s = v0.x*v0.x + v0.y*v0.y + v0.z*v0.z + v0.w*v0.w
            + v1.x*v1.x + v1.y*v1.y + v1.z*v1.z + v1.w*v1.w;
    #pragma unroll
    for (int o = 16; o > 0; o >>= 1)
        s += __shfl_xor_sync(0xFFFFFFFFu, s, o);   // all lanes get the sum

    const float q = 127.0f / fmaxf(sqrtf(s), EPS_F);

    // |x|*q <= 127 by construction -> int8 fits exactly, no clamp needed.
    int b0 = __float2int_rn(v0.x * q), b1 = __float2int_rn(v0.y * q);
    int b2 = __float2int_rn(v0.z * q), b3 = __float2int_rn(v0.w * q);
    int b4 = __float2int_rn(v1.x * q), b5 = __float2int_rn(v1.y * q);
    int b6 = __float2int_rn(v1.z * q), b7 = __float2int_rn(v1.w * q);

    uint2 u;
    u.x = (unsigned)(b0 & 0xFF) | ((unsigned)(b1 & 0xFF) << 8)
        | ((unsigned)(b2 & 0xFF) << 16) | ((unsigned)b3 << 24);
    u.y = (unsigned)(b4 & 0xFF) | ((unsigned)(b5 & 0xFF) << 8)
        | ((unsigned)(b6 & 0xFF) << 16) | ((unsigned)b7 << 24);

    // Row = 256 B; lane writes bytes [lane*8, lane*8+8).
    reinterpret_cast<uint2*>(g_pred_b)[row * 32 + lane] = u;
}

// Accumulate signed-int8 dot of two uint4 (16 bytes each) via dp4a.
__device__ __forceinline__ int dp16(uint4 a, uint4 b, int acc)
{
    acc = __dp4a((int)a.x, (int)b.x, acc);
    acc = __dp4a((int)a.y, (int)b.y, acc);
    acc = __dp4a((int)a.z, (int)b.z, acc);
    acc = __dp4a((int)a.w, (int)b.w, acc);
    return acc;
}

// Kernel 2: 8 lanes per triplet, 4 triplets per warp per iteration.
// Row = 16 uint4; lane covers uint4 indices {sub, sub+8} -> each segment-LDG
// is one aligned 128B line (6 wavefronts per triplet total).
// dot(a,p) - dot(a,n) is EXACT int32; only the quantization approximates.
__global__ void __launch_bounds__(WARPS_PER_BLOCK * 32, 6)
tl_triplet_kernel(const long long* __restrict__ anchor_idx,
                  const long long* __restrict__ pos_idx,
                  const long long* __restrict__ neg_idx,
                  float* __restrict__ out)
{
    const int lane = threadIdx.x & 31;
    const int wid  = threadIdx.x >> 5;
    const int seg  = lane >> 3;   // 0..3 : which triplet in this warp
    const int sub  = lane & 7;    // 0..7 : position within triplet
    const int gwarp = blockIdx.x * WARPS_PER_BLOCK + wid;

    float acc = 0.0f;

    #pragma unroll
    for (int it = 0; it < ITERS; it++) {
        const int t = (gwarp * ITERS + it) * 4 + seg;   // < T_TRIP by construction

        const int a = ((int)anchor_idx[t]) & ROW_MASK;  // identity for valid input
        const int p = ((int)pos_idx[t])    & ROW_MASK;
        const int n = ((int)neg_idx[t])    & ROW_MASK;

        const uint4* ra = g_pred_b + a * ROW_U4 + sub;
        const uint4* rp = g_pred_b + p * ROW_U4 + sub;
        const uint4* rn = g_pred_b + n * ROW_U4 + sub;

        // 6 independent LDG.128 per lane -> per-warp MLP stays high.
        uint4 a0 = ra[0], a1 = ra[8];
        uint4 p0 = rp[0], p1 = rp[8];
        uint4 n0 = rn[0], n1 = rn[8];

        int sap = dp16(a0, p0, 0);
        sap     = dp16(a1, p1, sap);
        int san = dp16(a0, n0, 0);
        san     = dp16(a1, n1, san);
        int d = sap - san;

        // Segmented butterfly (exact int adds) within each 8-lane group.
        #pragma unroll
        for (int o = 1; o < 8; o <<= 1)
            d += __shfl_xor_sync(0xFFFFFFFFu, d, o);

        // Every lane of the segment holds the segment sum.
        acc += fmaxf((float)d * (1.0f / 16129.0f) + MARGIN, 0.0f);
    }

    // Combine the 4 segments (lanes within a segment agree): each counted once.
    acc += __shfl_xor_sync(0xFFFFFFFFu, acc, 8);
    acc += __shfl_xor_sync(0xFFFFFFFFu, acc, 16);

    __shared__ float sacc[WARPS_PER_BLOCK];
    if (lane == 0) sacc[wid] = acc;
    __syncthreads();

    if (threadIdx.x == 0) {
        float sum = 0.0f;
        #pragma unroll
        for (int i = 0; i < WARPS_PER_BLOCK; i++) sum += sacc[i];
        atomicAdd(out, sum * (1.0f / (float)T_TRIP));
    }
}

extern "C" void kernel_launch(void* const* d_in, const int* in_sizes, int n_in,
                              void* d_out, int out_size)
{
    const float*     pred = (const float*)d_in[0];
    const long long* ai   = (const long long*)d_in[1];
    const long long* pi   = (const long long*)d_in[2];
    const long long* ni   = (const long long*)d_in[3];
    float* out = (float*)d_out;

    tl_normalize_kernel<<<B_ROWS / 8, 256>>>(pred, out);
    tl_triplet_kernel<<<TRIP_BLOCKS, WARPS_PER_BLOCK * 32>>>(ai, pi, ni, out);
}

// round 13
// speedup vs baseline: 1.4024x; 1.3034x over previous
#include <cuda_runtime.h>
#include <cstdint>

#define B_ROWS   16384
#define D_DIM    256
#define T_TRIP   262144
#define MARGIN   0.1f
#define EPS_F    1e-6f
#define ROW_MASK (B_ROWS - 1)

#define WARPS_PER_BLOCK 8
#define ITERS 4
// each warp-iteration handles 4 triplets (8 lanes per triplet)
// 2048 blocks * 8 warps * 4 iters * 4 triplets = 262144 == T_TRIP
#define TRIP_BLOCKS (T_TRIP / (WARPS_PER_BLOCK * ITERS * 4))

// Normalized int8 copy of pred: row r = round(127 * pred[r]/max(||pred[r]||,eps)).
// Row = 256 int8 = 256 B = 16 uint4. 4 MB device-global scratch, 16B-aligned.
#define ROW_U4 (D_DIM / 16)
__device__ uint4 g_pred_b[B_ROWS * ROW_U4];

// Kernel 1: one warp per row -> normalized int8 row. Zeroes d_out.
__global__ void __launch_bounds__(256)
tl_normalize_kernel(const float* __restrict__ pred, float* __restrict__ out)
{
    if (blockIdx.x == 0 && threadIdx.x == 0) out[0] = 0.0f;

    const int row  = (blockIdx.x * blockDim.x + threadIdx.x) >> 5;
    const int lane = threadIdx.x & 31;
    if (row >= B_ROWS) return;

    const float4* src = reinterpret_cast<const float4*>(pred + (size_t)row * D_DIM);
    float4 v0 = src[2 * lane];
    float4 v1 = src[2 * lane + 1];

    float s = v0.x*v0.x + v0.y*v0.y + v0.z*v0.z + v0.w*v0.w
            + v1.x*v1.x + v1.y*v1.y + v1.z*v1.z + v1.w*v1.w;
    #pragma unroll
    for (int o = 16; o > 0; o >>= 1)
        s += __shfl_xor_sync(0xFFFFFFFFu, s, o);

    const float q = 127.0f / fmaxf(sqrtf(s), EPS_F);

    int b0 = __float2int_rn(v0.x * q), b1 = __float2int_rn(v0.y * q);
    int b2 = __float2int_rn(v0.z * q), b3 = __float2int_rn(v0.w * q);
    int b4 = __float2int_rn(v1.x * q), b5 = __float2int_rn(v1.y * q);
    int b6 = __float2int_rn(v1.z * q), b7 = __float2int_rn(v1.w * q);

    uint2 u;
    u.x = (unsigned)(b0 & 0xFF) | ((unsigned)(b1 & 0xFF) << 8)
        | ((unsigned)(b2 & 0xFF) << 16) | ((unsigned)b3 << 24);
    u.y = (unsigned)(b4 & 0xFF) | ((unsigned)(b5 & 0xFF) << 8)
        | ((unsigned)(b6 & 0xFF) << 16) | ((unsigned)b7 << 24);

    reinterpret_cast<uint2*>(g_pred_b)[row * 32 + lane] = u;
}

__device__ __forceinline__ int dp16(uint4 a, uint4 b, int acc)
{
    acc = __dp4a((int)a.x, (int)b.x, acc);
    acc = __dp4a((int)a.y, (int)b.y, acc);
    acc = __dp4a((int)a.z, (int)b.z, acc);
    acc = __dp4a((int)a.w, (int)b.w, acc);
    return acc;
}

// Kernel 2: 8 lanes per triplet, 4 triplets per warp-iter, 4 iters per warp.
// ALL index loads issued first, then ALL 24 gather LDG.128s (96 data regs,
// launch_bounds(256,2) permits 128) -> ~24-deep per-warp MLP so gather
// latency is paid once per warp, not once per iteration.
__global__ void __launch_bounds__(WARPS_PER_BLOCK * 32, 2)
tl_triplet_kernel(const int* __restrict__ anchor_lo,   // int64 viewed as int pairs
                  const int* __restrict__ pos_lo,
                  const int* __restrict__ neg_lo,
                  float* __restrict__ out)
{
    const int lane = threadIdx.x & 31;
    const int wid  = threadIdx.x >> 5;
    const int seg  = lane >> 3;   // 0..3 : triplet within warp-iter
    const int sub  = lane & 7;    // 0..7 : position within triplet
    const int gwarp = blockIdx.x * WARPS_PER_BLOCK + wid;

    // ---- Phase 1: prefetch all indices (low 32 bits of each int64) ----
    int ia[ITERS], ip[ITERS], in_[ITERS];
    #pragma unroll
    for (int it = 0; it < ITERS; it++) {
        const int t = (gwarp * ITERS + it) * 4 + seg;   // < T_TRIP
        ia[it]  = anchor_lo[2 * t];
        ip[it]  = pos_lo[2 * t];
        in_[it] = neg_lo[2 * t];
    }

    // ---- Phase 2: issue all 24 gather LDG.128s ----
    uint4 A0[ITERS], A1[ITERS], P0[ITERS], P1[ITERS], N0[ITERS], N1[ITERS];
    #pragma unroll
    for (int it = 0; it < ITERS; it++) {
        const int a = ia[it]  & ROW_MASK;   // identity for valid input
        const int p = ip[it]  & ROW_MASK;
        const int n = in_[it] & ROW_MASK;
        const uint4* ra = g_pred_b + a * ROW_U4 + sub;
        const uint4* rp = g_pred_b + p * ROW_U4 + sub;
        const uint4* rn = g_pred_b + n * ROW_U4 + sub;
        A0[it] = ra[0]; A1[it] = ra[8];
        P0[it] = rp[0]; P1[it] = rp[8];
        N0[it] = rn[0]; N1[it] = rn[8];
    }

    // ---- Phase 3: compute (iterations independent -> overlappable) ----
    float acc = 0.0f;
    #pragma unroll
    for (int it = 0; it < ITERS; it++) {
        int sap = dp16(A0[it], P0[it], 0);
        int san = dp16(A0[it], N0[it], 0);
        sap = dp16(A1[it], P1[it], sap);
        san = dp16(A1[it], N1[it], san);
        int d = sap - san;

        #pragma unroll
        for (int o = 1; o < 8; o <<= 1)
            d += __shfl_xor_sync(0xFFFFFFFFu, d, o);

        acc += fmaxf((float)d * (1.0f / 16129.0f) + MARGIN, 0.0f);
    }

    // Combine the 4 segments (lanes within a segment agree): each counted once.
    acc += __shfl_xor_sync(0xFFFFFFFFu, acc, 8);
    acc += __shfl_xor_sync(0xFFFFFFFFu, acc, 16);

    __shared__ float sacc[WARPS_PER_BLOCK];
    if (lane == 0) sacc[wid] = acc;
    __syncthreads();

    if (threadIdx.x == 0) {
        float sum = 0.0f;
        #pragma unroll
        for (int i = 0; i < WARPS_PER_BLOCK; i++) sum += sacc[i];
        atomicAdd(out, sum * (1.0f / (float)T_TRIP));
    }
}

extern "C" void kernel_launch(void* const* d_in, const int* in_sizes, int n_in,
                              void* d_out, int out_size)
{
    const float* pred = (const float*)d_in[0];
    const int*   ai   = (const int*)d_in[1];   // int64 -> low-word access
    const int*   pi   = (const int*)d_in[2];
    const int*   ni   = (const int*)d_in[3];
    float* out = (float*)d_out;

    tl_normalize_kernel<<<B_ROWS / 8, 256>>>(pred, out);
    tl_triplet_kernel<<<TRIP_BLOCKS, WARPS_PER_BLOCK * 32>>>(ai, pi, ni, out);
}